// round 13
// baseline (speedup 1.0000x reference)
#include <cuda_runtime.h>

// y[b,c] = b_fc[c] + dot(h[b,0,:], V[c,:]),  V = W_fc @ W_emb  ([2,768])
// (TreeLSTM scan in the reference is dead code; adj and recurrent weights unused.)
// B=32, N=128, FI=768, FO=128.
//
// Two nodes with Programmatic Dependent Launch (best structure, R7):
// B launches while A streams W_emb; B preloads h, then griddepsync.
// This round: A rebuilt — 48 blocks, float4 loads, front-batched (MLP=8).

#define B_  32
#define N_  128
#define FI_ 768
#define FO_ 128
#define NQ  (FI_/4)     // 192 f-quads

__device__ float4 g_V[2][NQ];   // scratch: V = W_fc @ W_emb (quad layout)

// ---- Kernel A: V[c, f-quad] over 48 blocks x 256 threads ----
// Block owns 16 f-quads (64 f). Thread (og, q): og = t/16 (8 o's), q = t%16.
__global__ __launch_bounds__(256, 1)
void rvnn_precompute_V(const float* __restrict__ W_emb,  // [FO,FI]
                       const float* __restrict__ W_fc)   // [2,FO]
{
    cudaTriggerProgrammaticLaunchCompletion();   // let B launch immediately

    const int t  = threadIdx.x;
    const int og = t >> 4;                 // 0..15 (8 o's each)
    const int q  = (blockIdx.x << 4) + (t & 15);   // global f-quad

    const float4* wemb4 = reinterpret_cast<const float4*>(W_emb);

    // Front-batch: 8 independent LDG.128 + W_fc scalars.
    float4 w[8];
    float  f0[8], f1[8];
    #pragma unroll
    for (int j = 0; j < 8; ++j) {
        const int o = og * 8 + j;
        w[j]  = __ldg(&wemb4[(size_t)o * NQ + q]);
        f0[j] = __ldg(&W_fc[o]);
        f1[j] = __ldg(&W_fc[FO_ + o]);
    }

    float4 a0 = make_float4(0.f, 0.f, 0.f, 0.f);
    float4 a1 = make_float4(0.f, 0.f, 0.f, 0.f);
    #pragma unroll
    for (int j = 0; j < 8; ++j) {
        a0.x = fmaf(f0[j], w[j].x, a0.x); a0.y = fmaf(f0[j], w[j].y, a0.y);
        a0.z = fmaf(f0[j], w[j].z, a0.z); a0.w = fmaf(f0[j], w[j].w, a0.w);
        a1.x = fmaf(f1[j], w[j].x, a1.x); a1.y = fmaf(f1[j], w[j].y, a1.y);
        a1.z = fmaf(f1[j], w[j].z, a1.z); a1.w = fmaf(f1[j], w[j].w, a1.w);
    }

    __shared__ float4 sp[16][2][16];       // [og][c][local q]
    sp[og][0][t & 15] = a0;
    sp[og][1][t & 15] = a1;
    __syncthreads();

    // 32 threads fold 16 og-partials each -> one V quad.
    if (t < 32) {
        const int c = t >> 4, lq = t & 15;
        float4 s = make_float4(0.f, 0.f, 0.f, 0.f);
        #pragma unroll
        for (int k = 0; k < 16; ++k) {
            float4 p = sp[k][c][lq];
            s.x += p.x; s.y += p.y; s.z += p.z; s.w += p.w;
        }
        g_V[c][(blockIdx.x << 4) + lq] = s;
    }
}

// ---- Kernel B: y[b,c] = b_fc[c] + dot(h[b,0,:], V[c,:]) ----
__global__ __launch_bounds__(192, 1)
void rvnn_head_kernel(const float* __restrict__ h,    // [B,N,FI]
                      const float* __restrict__ b_fc, // [2]
                      float* __restrict__ y)          // [B,2]
{
    const int b    = blockIdx.x;
    const int t    = threadIdx.x;           // 0..191
    const int warp = t >> 5;                // 0..5
    const int lane = t & 31;

    // h loads issue while kernel A is still running (PDL overlap).
    const float4* hrow = reinterpret_cast<const float4*>(h + (size_t)b * N_ * FI_);
    float4 hv = __ldg(&hrow[t]);
    const float bf0 = __ldg(&b_fc[0]);
    const float bf1 = __ldg(&b_fc[1]);

    cudaGridDependencySynchronize();        // wait for A's g_V writes

    float4 v0 = g_V[0][t];
    float4 v1 = g_V[1][t];

    float a0 = fmaf(hv.x, v0.x, fmaf(hv.y, v0.y, fmaf(hv.z, v0.z, hv.w * v0.w)));
    float a1 = fmaf(hv.x, v1.x, fmaf(hv.y, v1.y, fmaf(hv.z, v1.z, hv.w * v1.w)));

    #pragma unroll
    for (int off = 16; off > 0; off >>= 1) {
        a0 += __shfl_down_sync(0xffffffffu, a0, off);
        a1 += __shfl_down_sync(0xffffffffu, a1, off);
    }

    __shared__ float w0[6], w1[6];
    if (lane == 0) { w0[warp] = a0; w1[warp] = a1; }
    __syncthreads();

    if (t == 0) {
        float s0 = w0[0] + w0[1] + w0[2] + w0[3] + w0[4] + w0[5];
        float s1 = w1[0] + w1[1] + w1[2] + w1[3] + w1[4] + w1[5];
        y[b * 2 + 0] = s0 + bf0;
        y[b * 2 + 1] = s1 + bf1;
    }
}

extern "C" void kernel_launch(void* const* d_in, const int* in_sizes, int n_in,
                              void* d_out, int out_size)
{
    // metadata order: h, adj, W_emb, W_ioux, b_ioux, W_iouh, b_iouh,
    //                 W_coux, b_coux, W_couh, b_couh, W_fc, b_fc
    const float* h     = (const float*)d_in[0];
    const float* W_emb = (const float*)d_in[2];
    const float* W_fc  = (const float*)d_in[11];
    const float* b_fc  = (const float*)d_in[12];
    float* y = (float*)d_out;

    rvnn_precompute_V<<<NQ / 16, 256>>>(W_emb, W_fc);

    cudaLaunchConfig_t cfg = {};
    cfg.gridDim  = dim3(B_, 1, 1);
    cfg.blockDim = dim3(192, 1, 1);
    cfg.dynamicSmemBytes = 0;
    cfg.stream = 0;
    cudaLaunchAttribute attrs[1];
    attrs[0].id = cudaLaunchAttributeProgrammaticStreamSerialization;
    attrs[0].val.programmaticStreamSerializationAllowed = 1;
    cfg.attrs = attrs;
    cfg.numAttrs = 1;
    cudaLaunchKernelEx(&cfg, rvnn_head_kernel, h, b_fc, y);
}

// round 14
// speedup vs baseline: 1.1157x; 1.1157x over previous
#include <cuda_runtime.h>

// y[b,c] = b_fc[c] + dot(h[b,0,:], V[c,:]),  V = W_fc @ W_emb  ([2,768])
// (TreeLSTM scan in the reference is dead code; adj and recurrent weights unused.)
// B=32, N=128, FI=768, FO=128.
//
// Two nodes with Programmatic Dependent Launch (best structure, R7):
// B launches while A streams W_emb; B preloads h, then griddepsync.
// R14: A keeps R7's 24-block ramp but loads W_emb as 4 front-batched float4
// per thread (1/4 the LDG count of R7's scalar A). B identical to R7.

#define B_  32
#define N_  128
#define FI_ 768
#define FO_ 128
#define NQ  (FI_/4)     // 192 f-quads

__device__ float4 g_V[2][NQ];   // scratch: V = W_fc @ W_emb (quad layout)

// ---- Kernel A: 24 blocks x 256 threads. Block owns 8 f-quads (32 f). ----
// Thread: og = t>>3 (one of 32 o-groups, 4 o's each), lq = t&7 (local quad).
__global__ __launch_bounds__(256, 1)
void rvnn_precompute_V(const float* __restrict__ W_emb,  // [FO,FI]
                       const float* __restrict__ W_fc)   // [2,FO]
{
    cudaTriggerProgrammaticLaunchCompletion();   // let B launch immediately

    const int t  = threadIdx.x;
    const int og = t >> 3;                  // 0..31 (4 o's each)
    const int lq = t & 7;                   // 0..7
    const int q  = (blockIdx.x << 3) + lq;  // global f-quad

    const float4* wemb4 = reinterpret_cast<const float4*>(W_emb);

    // Front-batch: 4 independent LDG.128 (coalesced: 8 lanes x 16B contiguous
    // per o-row) + 8 broadcast W_fc scalars.
    float4 w[4];
    float  f0[4], f1[4];
    #pragma unroll
    for (int j = 0; j < 4; ++j) {
        const int o = og * 4 + j;
        w[j]  = __ldg(&wemb4[(size_t)o * NQ + q]);
        f0[j] = __ldg(&W_fc[o]);
        f1[j] = __ldg(&W_fc[FO_ + o]);
    }

    float4 a0 = make_float4(0.f, 0.f, 0.f, 0.f);
    float4 a1 = make_float4(0.f, 0.f, 0.f, 0.f);
    #pragma unroll
    for (int j = 0; j < 4; ++j) {
        a0.x = fmaf(f0[j], w[j].x, a0.x); a0.y = fmaf(f0[j], w[j].y, a0.y);
        a0.z = fmaf(f0[j], w[j].z, a0.z); a0.w = fmaf(f0[j], w[j].w, a0.w);
        a1.x = fmaf(f1[j], w[j].x, a1.x); a1.y = fmaf(f1[j], w[j].y, a1.y);
        a1.z = fmaf(f1[j], w[j].z, a1.z); a1.w = fmaf(f1[j], w[j].w, a1.w);
    }

    __shared__ float4 sp[32][2][8];         // [og][c][lq]
    sp[og][0][lq] = a0;
    sp[og][1][lq] = a1;
    __syncthreads();

    // 16 threads fold 32 og-partials each -> one V quad.
    if (t < 16) {
        const int c = t >> 3, l = t & 7;
        float4 s = make_float4(0.f, 0.f, 0.f, 0.f);
        #pragma unroll
        for (int k = 0; k < 32; ++k) {
            float4 p = sp[k][c][l];
            s.x += p.x; s.y += p.y; s.z += p.z; s.w += p.w;
        }
        g_V[c][(blockIdx.x << 3) + l] = s;
    }
}

// ---- Kernel B: y[b,c] = b_fc[c] + dot(h[b,0,:], V[c,:]) ----
__global__ __launch_bounds__(192, 1)
void rvnn_head_kernel(const float* __restrict__ h,    // [B,N,FI]
                      const float* __restrict__ b_fc, // [2]
                      float* __restrict__ y)          // [B,2]
{
    const int b    = blockIdx.x;
    const int t    = threadIdx.x;           // 0..191
    const int warp = t >> 5;                // 0..5
    const int lane = t & 31;

    // h + bias loads issue while kernel A is still running (PDL overlap).
    const float4* hrow = reinterpret_cast<const float4*>(h + (size_t)b * N_ * FI_);
    float4 hv = __ldg(&hrow[t]);
    const float bf0 = __ldg(&b_fc[0]);
    const float bf1 = __ldg(&b_fc[1]);

    cudaGridDependencySynchronize();        // wait for A's g_V writes

    float4 v0 = g_V[0][t];
    float4 v1 = g_V[1][t];

    float a0 = fmaf(hv.x, v0.x, fmaf(hv.y, v0.y, fmaf(hv.z, v0.z, hv.w * v0.w)));
    float a1 = fmaf(hv.x, v1.x, fmaf(hv.y, v1.y, fmaf(hv.z, v1.z, hv.w * v1.w)));

    #pragma unroll
    for (int off = 16; off > 0; off >>= 1) {
        a0 += __shfl_down_sync(0xffffffffu, a0, off);
        a1 += __shfl_down_sync(0xffffffffu, a1, off);
    }

    __shared__ float w0[6], w1[6];
    if (lane == 0) { w0[warp] = a0; w1[warp] = a1; }
    __syncthreads();

    if (t == 0) {
        float s0 = w0[0] + w0[1] + w0[2] + w0[3] + w0[4] + w0[5];
        float s1 = w1[0] + w1[1] + w1[2] + w1[3] + w1[4] + w1[5];
        y[b * 2 + 0] = s0 + bf0;
        y[b * 2 + 1] = s1 + bf1;
    }
}

extern "C" void kernel_launch(void* const* d_in, const int* in_sizes, int n_in,
                              void* d_out, int out_size)
{
    // metadata order: h, adj, W_emb, W_ioux, b_ioux, W_iouh, b_iouh,
    //                 W_coux, b_coux, W_couh, b_couh, W_fc, b_fc
    const float* h     = (const float*)d_in[0];
    const float* W_emb = (const float*)d_in[2];
    const float* W_fc  = (const float*)d_in[11];
    const float* b_fc  = (const float*)d_in[12];
    float* y = (float*)d_out;

    rvnn_precompute_V<<<NQ / 8, 256>>>(W_emb, W_fc);   // 24 blocks (R7 ramp)

    cudaLaunchConfig_t cfg = {};
    cfg.gridDim  = dim3(B_, 1, 1);
    cfg.blockDim = dim3(192, 1, 1);
    cfg.dynamicSmemBytes = 0;
    cfg.stream = 0;
    cudaLaunchAttribute attrs[1];
    attrs[0].id = cudaLaunchAttributeProgrammaticStreamSerialization;
    attrs[0].val.programmaticStreamSerializationAllowed = 1;
    cfg.attrs = attrs;
    cfg.numAttrs = 1;
    cudaLaunchKernelEx(&cfg, rvnn_head_kernel, h, b_fc, y);
}